// round 10
// baseline (speedup 1.0000x reference)
#include <cuda_runtime.h>

#define MAXN 100000
#define HID 64
#define CAP 64   // neighbor-list capacity per node (deg ~ Poisson(16))

// Scratch (no cudaMalloc allowed)
__device__ float g_bufY[(size_t)MAXN * HID];    // 25.6 MB
__device__ float g_bufAgg[(size_t)MAXN * HID];  // 25.6 MB
__device__ int   g_cnt[MAXN];                   // 0.4 MB
__device__ int   g_buck[(size_t)MAXN * CAP];    // 25.6 MB

typedef unsigned long long ull;

// ---------------------------------------------------------------------------
// f32x2 packed helpers (Blackwell FFMA2 — PTX-only, 2 FMAs per issue)
// ---------------------------------------------------------------------------
__device__ __forceinline__ void fma2(ull& d, ull a, ull b) {
    asm("fma.rn.f32x2 %0, %1, %2, %0;" : "+l"(d) : "l"(a), "l"(b));
}
__device__ __forceinline__ ull dup2(float a) {
    ull r;
    asm("mov.b64 %0, {%1, %1};" : "=l"(r) : "f"(a));
    return r;
}
__device__ __forceinline__ float2 unpack2(ull v) {
    float2 f;
    asm("mov.b64 {%0, %1}, %2;" : "=f"(f.x), "=f"(f.y) : "l"(v));
    return f;
}

// ---------------------------------------------------------------------------
// Neighbor-list build: cnt[d]=in-degree, buck[d*CAP+slot]=src
// ---------------------------------------------------------------------------
__global__ void zero_cnt_kernel(int* cnt, int N) {
    int i = blockIdx.x * blockDim.x + threadIdx.x;
    if (i < N) cnt[i] = 0;
}

__global__ void build_kernel(const int* __restrict__ ei,
                             int* cnt, int* buck, int E) {
    int e = blockIdx.x * blockDim.x + threadIdx.x;
    if (e >= E) return;
    int s = __ldg(&ei[e]);
    int d = __ldg(&ei[E + e]);
    int slot = atomicAdd(&cnt[d], 1);
    if (slot < CAP) buck[(size_t)d * CAP + slot] = s;
}

// ---------------------------------------------------------------------------
// GEMM: out[64 rows, 64] = act(X[N,K]) @ W[K,64]
// Duplicated-X smem: each a value stored twice adjacent so the f32x2
// broadcast operand is a single LDS.64 (no dup2 MOVs in the inner loop).
// K processed in KH=min(K,64)-wide phases reusing one dup buffer.
// Inner loop per k: 2 LDS.64 (W) + 4 LDS.64 (A) + 8 FFMA2 = 14 issues
// vs 16 FMA-pipe cycles -> pipe-bound.
// ---------------------------------------------------------------------------
template<int K, bool PRE>
__global__ void __launch_bounds__(256) gemm64_kernel(
        const float* X,
        const float* __restrict__ W,
        const float* __restrict__ bpre,
        float* __restrict__ outY,
        int N) {
    constexpr int KH  = (K < 64) ? K : 64;   // phase width
    constexpr int NPH = K / KH;              // number of phases
    constexpr int LDD = 2 * KH + 2;          // floats; even -> 8B aligned rows
    extern __shared__ float smem[];
    float* Xd = smem;                        // [64][LDD] duplicated X (phase)
    float* Ws = smem + 64 * LDD;             // [K][64]

    const int tid  = threadIdx.x;
    const int row0 = blockIdx.x * 64;

    {   // W tile (full K)
        float4* Ws4 = (float4*)Ws;
        const float4* Wg4 = (const float4*)W;
        for (int i = tid; i < K * 16; i += 256) Ws4[i] = Wg4[i];
    }

    const int tx = tid & 15;                 // cols tx*4 .. tx*4+3
    const int ty = tid >> 4;                 // rows ty*4 .. ty*4+3

    ull acc[4][2];
    #pragma unroll
    for (int i = 0; i < 4; ++i) { acc[i][0] = 0ull; acc[i][1] = 0ull; }

    const ull* Wsq = (const ull*)Ws;

    #pragma unroll
    for (int ph = 0; ph < NPH; ++ph) {
        if (ph > 0) __syncthreads();         // drain previous-phase readers

        // load X columns [ph*KH, ph*KH+KH), duplicated, optional relu(x+b)
        constexpr int KV = KH / 4;
        for (int i = tid; i < 64 * KV; i += 256) {
            int r  = i / KV;
            int c4 = i % KV;
            int col = ph * KH + c4 * 4;
            float4 v = make_float4(0.f, 0.f, 0.f, 0.f);
            if (row0 + r < N)
                v = *(const float4*)(X + (size_t)(row0 + r) * K + col);
            if (PRE) {
                v.x = fmaxf(v.x + __ldg(&bpre[col + 0]), 0.f);
                v.y = fmaxf(v.y + __ldg(&bpre[col + 1]), 0.f);
                v.z = fmaxf(v.z + __ldg(&bpre[col + 2]), 0.f);
                v.w = fmaxf(v.w + __ldg(&bpre[col + 3]), 0.f);
            }
            ull* dst = (ull*)(Xd + r * LDD + 2 * c4 * 4);
            dst[0] = dup2(v.x);
            dst[1] = dup2(v.y);
            dst[2] = dup2(v.z);
            dst[3] = dup2(v.w);
        }
        __syncthreads();

        #pragma unroll 8
        for (int k = 0; k < KH; ++k) {
            int kg = ph * KH + k;
            ull w01 = Wsq[kg * 32 + tx * 2 + 0];
            ull w23 = Wsq[kg * 32 + tx * 2 + 1];
            #pragma unroll
            for (int i = 0; i < 4; ++i) {
                ull aa = *(const ull*)(Xd + (ty * 4 + i) * LDD + 2 * k);
                fma2(acc[i][0], aa, w01);
                fma2(acc[i][1], aa, w23);
            }
        }
    }

    #pragma unroll
    for (int i = 0; i < 4; ++i) {
        int r = row0 + ty * 4 + i;
        if (r < N) {
            float2 p0 = unpack2(acc[i][0]);
            float2 p1 = unpack2(acc[i][1]);
            *(float4*)(outY + (size_t)r * 64 + tx * 4) =
                make_float4(p0.x, p0.y, p1.x, p1.y);
        }
    }
}

// ---------------------------------------------------------------------------
// Gather core (at LTS cap; 4-way unroll, 2 accumulators)
// ---------------------------------------------------------------------------
__device__ __forceinline__ float4 gather_row(const int* __restrict__ cnt,
                                             const int* __restrict__ buck,
                                             const float* __restrict__ Y,
                                             int n, int c) {
    float4 a0 = __ldg((const float4*)(Y + (size_t)n * 64) + c);  // self term
    float4 a1 = make_float4(0.f, 0.f, 0.f, 0.f);
    int m = min(__ldg(&cnt[n]), CAP);
    const int* b = buck + (size_t)n * CAP;

    int j = 0;
    for (; j + 4 <= m; j += 4) {
        int s0 = __ldg(&b[j]);
        int s1 = __ldg(&b[j + 1]);
        int s2 = __ldg(&b[j + 2]);
        int s3 = __ldg(&b[j + 3]);
        float4 v0 = __ldg((const float4*)(Y + (size_t)s0 * 64) + c);
        float4 v1 = __ldg((const float4*)(Y + (size_t)s1 * 64) + c);
        float4 v2 = __ldg((const float4*)(Y + (size_t)s2 * 64) + c);
        float4 v3 = __ldg((const float4*)(Y + (size_t)s3 * 64) + c);
        a0.x += v0.x + v1.x;  a0.y += v0.y + v1.y;
        a0.z += v0.z + v1.z;  a0.w += v0.w + v1.w;
        a1.x += v2.x + v3.x;  a1.y += v2.y + v3.y;
        a1.z += v2.z + v3.z;  a1.w += v2.w + v3.w;
    }
    for (; j < m; ++j) {
        int s0 = __ldg(&b[j]);
        float4 v0 = __ldg((const float4*)(Y + (size_t)s0 * 64) + c);
        a0.x += v0.x; a0.y += v0.y; a0.z += v0.z; a0.w += v0.w;
    }
    a0.x += a1.x; a0.y += a1.y; a0.z += a1.z; a0.w += a1.w;
    return a0;
}

__global__ void gather_kernel(const int* __restrict__ cnt,
                              const int* __restrict__ buck,
                              const float* __restrict__ Y,
                              float* __restrict__ Agg,
                              int N) {
    int t = blockIdx.x * blockDim.x + threadIdx.x;
    int n = t >> 4;
    int c = t & 15;
    if (n >= N) return;
    float4 acc = gather_row(cnt, buck, Y, n, c);
    *((float4*)(Agg + (size_t)n * 64) + c) = acc;
}

// ---------------------------------------------------------------------------
// Fused layer-2 aggregation + MLP head
// ---------------------------------------------------------------------------
__global__ void gather_head_kernel(const int* __restrict__ cnt,
                                   const int* __restrict__ buck,
                                   const float* __restrict__ Y,
                                   const float* __restrict__ b2,
                                   const float* __restrict__ W3,
                                   const float* __restrict__ b3,
                                   const float* __restrict__ W4,
                                   const float* __restrict__ b4,
                                   float* __restrict__ out,
                                   int N) {
    __shared__ float W3s[64 * 16];
    __shared__ float b2s[64], b3s[16], W4s[16];
    __shared__ float h2s[16][64];        // 16 nodes per 256-thread block

    const int tid = threadIdx.x;
    for (int i = tid; i < 64 * 16; i += 256) W3s[i] = W3[i];
    if (tid < 64) b2s[tid] = b2[tid];
    if (tid < 16) { b3s[tid] = b3[tid]; W4s[tid] = W4[tid]; }
    __syncthreads();

    int t = blockIdx.x * 256 + tid;
    int n = t >> 4;
    int c = t & 15;                      // float4 column / W3 output index
    int g = tid >> 4;                    // node slot within block
    if (n >= N) return;

    float4 acc = gather_row(cnt, buck, Y, n, c);

    float4 h;
    h.x = fmaxf(acc.x + b2s[4 * c + 0], 0.f);
    h.y = fmaxf(acc.y + b2s[4 * c + 1], 0.f);
    h.z = fmaxf(acc.z + b2s[4 * c + 2], 0.f);
    h.w = fmaxf(acc.w + b2s[4 * c + 3], 0.f);
    *(float4*)(&h2s[g][4 * c]) = h;
    __syncwarp();

    float a3 = b3s[c];
    #pragma unroll 16
    for (int k = 0; k < 64; ++k)
        a3 += h2s[g][k] * W3s[k * 16 + c];
    float v = fmaxf(a3, 0.f) * W4s[c];

    #pragma unroll
    for (int off = 8; off > 0; off >>= 1)
        v += __shfl_xor_sync(0xffffffffu, v, off, 16);

    if (c == 0) out[n] = v + __ldg(&b4[0]);
}

// ---------------------------------------------------------------------------
extern "C" void kernel_launch(void* const* d_in, const int* in_sizes, int n_in,
                              void* d_out, int out_size) {
    const float* x  = (const float*)d_in[0];
    const int*   ei = (const int*)d_in[1];     // int32 (JAX x64 disabled)
    const float* W1 = (const float*)d_in[2];
    const float* b1 = (const float*)d_in[3];
    const float* W2 = (const float*)d_in[4];
    const float* b2 = (const float*)d_in[5];
    const float* W3 = (const float*)d_in[6];
    const float* b3 = (const float*)d_in[7];
    const float* W4 = (const float*)d_in[8];
    const float* b4 = (const float*)d_in[9];
    float* out = (float*)d_out;

    const int N = in_sizes[0] / 128;     // 100000
    const int E = in_sizes[1] / 2;       // 1600000

    float *bufY, *bufAgg;
    int *cnt, *buck;
    cudaGetSymbolAddress((void**)&bufY, g_bufY);
    cudaGetSymbolAddress((void**)&bufAgg, g_bufAgg);
    cudaGetSymbolAddress((void**)&cnt, g_cnt);
    cudaGetSymbolAddress((void**)&buck, g_buck);

    // smem: Xd [64][2*KH+2] + Ws [K][64]
    const int smem1 = (64 * (2 * 64 + 2) + 128 * 64) * (int)sizeof(float); // 66048
    const int smem2 = (64 * (2 * 64 + 2) + 64 * 64)  * (int)sizeof(float); // 49664
    cudaFuncSetAttribute((const void*)gemm64_kernel<128, false>,
                         cudaFuncAttributeMaxDynamicSharedMemorySize, smem1);
    cudaFuncSetAttribute((const void*)gemm64_kernel<64, true>,
                         cudaFuncAttributeMaxDynamicSharedMemorySize, smem2);

    const int gb  = (N + 63) / 64;
    const int agb = (int)(((long long)N * 16 + 255) / 256);

    // Build neighbor lists (idempotent; rebuilt every call/replay)
    zero_cnt_kernel<<<(N + 255) / 256, 256>>>(cnt, N);
    build_kernel<<<(E + 255) / 256, 256>>>(ei, cnt, buck, E);

    // conv1: y1 = x@W1 ; agg1 = y1 + gather(y1)
    gemm64_kernel<128, false><<<gb, 256, smem1>>>(x, W1, nullptr, bufY, N);
    gather_kernel<<<agb, 256>>>(cnt, buck, bufY, bufAgg, N);
    // conv2: y2 = relu(agg1+b1)@W2
    gemm64_kernel<64, true><<<gb, 256, smem2>>>(bufAgg, W2, b1, bufY, N);
    // fused: agg2 = y2 + gather(y2); head MLP -> out
    gather_head_kernel<<<agb, 256>>>(cnt, buck, bufY, b2, W3, b3, W4, b4, out, N);
}

// round 11
// speedup vs baseline: 1.1219x; 1.1219x over previous
#include <cuda_runtime.h>

#define MAXN 100000
#define HID 64
#define CAP 64   // neighbor-list capacity per node (deg ~ Poisson(16))

// Scratch (no cudaMalloc allowed). __device__ globals are zero-initialized,
// so g_cnt starts at 0; gather_head_kernel re-zeroes it after last use,
// keeping the invariant across calls and graph replays.
__device__ float g_bufY[(size_t)MAXN * HID];    // 25.6 MB
__device__ float g_bufAgg[(size_t)MAXN * HID];  // 25.6 MB
__device__ int   g_cnt[MAXN];                   // 0.4 MB
__device__ int   g_buck[(size_t)MAXN * CAP];    // 25.6 MB

typedef unsigned long long ull;

// ---------------------------------------------------------------------------
// f32x2 packed helpers (Blackwell FFMA2 — PTX-only, 2 FMAs per issue)
// ---------------------------------------------------------------------------
__device__ __forceinline__ void fma2(ull& d, ull a, ull b) {
    asm("fma.rn.f32x2 %0, %1, %2, %0;" : "+l"(d) : "l"(a), "l"(b));
}
__device__ __forceinline__ ull dup2(float a) {
    ull r;
    asm("mov.b64 %0, {%1, %1};" : "=l"(r) : "f"(a));
    return r;
}
__device__ __forceinline__ ull pack2(float lo, float hi) {
    ull r;
    asm("mov.b64 %0, {%1, %2};" : "=l"(r) : "f"(lo), "f"(hi));
    return r;
}
__device__ __forceinline__ float2 unpack2(ull v) {
    float2 f;
    asm("mov.b64 {%0, %1}, %2;" : "=f"(f.x), "=f"(f.y) : "l"(v));
    return f;
}

// ---------------------------------------------------------------------------
// Neighbor-list build: cnt[d]=in-degree, buck[d*CAP+slot]=src
// 2 edges per thread via int2 loads (E is even: 1.6M).
// ---------------------------------------------------------------------------
__global__ void build_kernel(const int* __restrict__ ei,
                             int* cnt, int* buck, int E) {
    int t = blockIdx.x * blockDim.x + threadIdx.x;
    int e = t * 2;
    if (e >= E) return;
    int2 s2 = __ldg((const int2*)(ei + e));
    int2 d2 = __ldg((const int2*)(ei + E + e));
    int slot0 = atomicAdd(&cnt[d2.x], 1);
    if (slot0 < CAP) buck[(size_t)d2.x * CAP + slot0] = s2.x;
    if (e + 1 < E) {
        int slot1 = atomicAdd(&cnt[d2.y], 1);
        if (slot1 < CAP) buck[(size_t)d2.y * CAP + slot1] = s2.y;
    }
}

// ---------------------------------------------------------------------------
// GEMM body (R6-proven, DO NOT TOUCH): out[64 rows, 64] = act(X) @ W
// 256 threads, 4 rows x 4 cols micro-tile, f32x2 col-pair accumulators.
// ---------------------------------------------------------------------------
template<int K, bool PRE>
__global__ void gemm64_kernel(const float* X,
                              const float* __restrict__ W,
                              const float* __restrict__ bpre,
                              float* __restrict__ outY,
                              int N) {
    constexpr int LD = K + 4;
    constexpr int KV = K / 4;
    extern __shared__ float smem[];
    float* Xs = smem;                    // [64][LD]
    float* Ws = smem + 64 * LD;          // [K][64]

    const int tid  = threadIdx.x;
    const int row0 = blockIdx.x * 64;

    {   // W tile
        float4* Ws4 = (float4*)Ws;
        const float4* Wg4 = (const float4*)W;
        for (int i = tid; i < K * 16; i += 256) Ws4[i] = Wg4[i];
    }
    // X tile, optional fused relu(x+b)
    for (int i = tid; i < 64 * KV; i += 256) {
        int r  = i / KV;
        int c4 = i % KV;
        float4 v = make_float4(0.f, 0.f, 0.f, 0.f);
        if (row0 + r < N)
            v = *(const float4*)(X + (size_t)(row0 + r) * K + c4 * 4);
        if (PRE) {
            v.x = fmaxf(v.x + __ldg(&bpre[c4 * 4 + 0]), 0.f);
            v.y = fmaxf(v.y + __ldg(&bpre[c4 * 4 + 1]), 0.f);
            v.z = fmaxf(v.z + __ldg(&bpre[c4 * 4 + 2]), 0.f);
            v.w = fmaxf(v.w + __ldg(&bpre[c4 * 4 + 3]), 0.f);
        }
        *(float4*)(Xs + r * LD + c4 * 4) = v;
    }
    __syncthreads();

    const int tx = tid & 15;             // cols tx*4 .. tx*4+3  (2 col-pairs)
    const int ty = tid >> 4;             // rows ty*4 .. ty*4+3

    ull acc[4][2];
    #pragma unroll
    for (int i = 0; i < 4; ++i) { acc[i][0] = 0ull; acc[i][1] = 0ull; }

    const ull* Wsq = (const ull*)Ws;
    #pragma unroll 8
    for (int k = 0; k < K; ++k) {
        ull w01 = Wsq[k * 32 + tx * 2 + 0];
        ull w23 = Wsq[k * 32 + tx * 2 + 1];
        #pragma unroll
        for (int i = 0; i < 4; ++i) {
            ull aa = dup2(Xs[(ty * 4 + i) * LD + k]);
            fma2(acc[i][0], aa, w01);
            fma2(acc[i][1], aa, w23);
        }
    }

    #pragma unroll
    for (int i = 0; i < 4; ++i) {
        int r = row0 + ty * 4 + i;
        if (r < N) {
            float2 p0 = unpack2(acc[i][0]);
            float2 p1 = unpack2(acc[i][1]);
            *(float4*)(outY + (size_t)r * 64 + tx * 4) =
                make_float4(p0.x, p0.y, p1.x, p1.y);
        }
    }
}

// ---------------------------------------------------------------------------
// Gather core (at LTS roofline; 4-way unroll, 2 accumulators)
// ---------------------------------------------------------------------------
__device__ __forceinline__ float4 gather_row(const int* __restrict__ cnt,
                                             const int* __restrict__ buck,
                                             const float* __restrict__ Y,
                                             int n, int c) {
    float4 a0 = __ldg((const float4*)(Y + (size_t)n * 64) + c);  // self term
    float4 a1 = make_float4(0.f, 0.f, 0.f, 0.f);
    int m = min(__ldg(&cnt[n]), CAP);
    const int* b = buck + (size_t)n * CAP;

    int j = 0;
    for (; j + 4 <= m; j += 4) {
        int s0 = __ldg(&b[j]);
        int s1 = __ldg(&b[j + 1]);
        int s2 = __ldg(&b[j + 2]);
        int s3 = __ldg(&b[j + 3]);
        float4 v0 = __ldg((const float4*)(Y + (size_t)s0 * 64) + c);
        float4 v1 = __ldg((const float4*)(Y + (size_t)s1 * 64) + c);
        float4 v2 = __ldg((const float4*)(Y + (size_t)s2 * 64) + c);
        float4 v3 = __ldg((const float4*)(Y + (size_t)s3 * 64) + c);
        a0.x += v0.x + v1.x;  a0.y += v0.y + v1.y;
        a0.z += v0.z + v1.z;  a0.w += v0.w + v1.w;
        a1.x += v2.x + v3.x;  a1.y += v2.y + v3.y;
        a1.z += v2.z + v3.z;  a1.w += v2.w + v3.w;
    }
    for (; j < m; ++j) {
        int s0 = __ldg(&b[j]);
        float4 v0 = __ldg((const float4*)(Y + (size_t)s0 * 64) + c);
        a0.x += v0.x; a0.y += v0.y; a0.z += v0.z; a0.w += v0.w;
    }
    a0.x += a1.x; a0.y += a1.y; a0.z += a1.z; a0.w += a1.w;
    return a0;
}

__global__ void gather_kernel(const int* __restrict__ cnt,
                              const int* __restrict__ buck,
                              const float* __restrict__ Y,
                              float* __restrict__ Agg,
                              int N) {
    int t = blockIdx.x * blockDim.x + threadIdx.x;
    int n = t >> 4;
    int c = t & 15;
    if (n >= N) return;
    float4 acc = gather_row(cnt, buck, Y, n, c);
    *((float4*)(Agg + (size_t)n * 64) + c) = acc;
}

// ---------------------------------------------------------------------------
// Fused layer-2 aggregation + MLP head (+ cnt reset for next call)
// W3 packed in k-pairs -> 32x(2 LDS.64 + 1 FFMA2) inner loop.
// ---------------------------------------------------------------------------
__global__ void gather_head_kernel(int* __restrict__ cnt,
                                   const int* __restrict__ buck,
                                   const float* __restrict__ Y,
                                   const float* __restrict__ b2,
                                   const float* __restrict__ W3,
                                   const float* __restrict__ b3,
                                   const float* __restrict__ W4,
                                   const float* __restrict__ b4,
                                   float* __restrict__ out,
                                   int N) {
    __shared__ ull   W3p[32 * 16];       // [kp][c] = (W3[2kp][c], W3[2kp+1][c])
    __shared__ float b2s[64], b3s[16], W4s[16];
    __shared__ float h2s[16][64];        // 16 nodes per 256-thread block

    const int tid = threadIdx.x;
    for (int i = tid; i < 32 * 16; i += 256) {
        int kp = i >> 4, c = i & 15;
        W3p[i] = pack2(__ldg(&W3[(2 * kp) * 16 + c]),
                       __ldg(&W3[(2 * kp + 1) * 16 + c]));
    }
    if (tid < 64) b2s[tid] = b2[tid];
    if (tid < 16) { b3s[tid] = b3[tid]; W4s[tid] = W4[tid]; }
    __syncthreads();

    int t = blockIdx.x * 256 + tid;
    int n = t >> 4;
    int c = t & 15;                      // float4 column / W3 output index
    int g = tid >> 4;                    // node slot within block
    if (n >= N) return;

    float4 acc = gather_row(cnt, buck, Y, n, c);

    float4 h;
    h.x = fmaxf(acc.x + b2s[4 * c + 0], 0.f);
    h.y = fmaxf(acc.y + b2s[4 * c + 1], 0.f);
    h.z = fmaxf(acc.z + b2s[4 * c + 2], 0.f);
    h.w = fmaxf(acc.w + b2s[4 * c + 3], 0.f);
    *(float4*)(&h2s[g][4 * c]) = h;
    __syncwarp();

    // a3 = b3[c] + sum_k h2[k]*W3[k][c], k in pairs via FFMA2
    ull a2 = 0ull;
    const ull* hq = (const ull*)h2s[g];
    #pragma unroll 8
    for (int kp = 0; kp < 32; ++kp)
        fma2(a2, hq[kp], W3p[kp * 16 + c]);
    float2 ap = unpack2(a2);
    float a3 = b3s[c] + ap.x + ap.y;
    float v = fmaxf(a3, 0.f) * W4s[c];

    #pragma unroll
    for (int off = 8; off > 0; off >>= 1)
        v += __shfl_xor_sync(0xffffffffu, v, off, 16);

    if (c == 0) {
        out[n] = v + __ldg(&b4[0]);
        cnt[n] = 0;                      // reset for next call / graph replay
    }
}

// ---------------------------------------------------------------------------
extern "C" void kernel_launch(void* const* d_in, const int* in_sizes, int n_in,
                              void* d_out, int out_size) {
    const float* x  = (const float*)d_in[0];
    const int*   ei = (const int*)d_in[1];     // int32 (JAX x64 disabled)
    const float* W1 = (const float*)d_in[2];
    const float* b1 = (const float*)d_in[3];
    const float* W2 = (const float*)d_in[4];
    const float* b2 = (const float*)d_in[5];
    const float* W3 = (const float*)d_in[6];
    const float* b3 = (const float*)d_in[7];
    const float* W4 = (const float*)d_in[8];
    const float* b4 = (const float*)d_in[9];
    float* out = (float*)d_out;

    const int N = in_sizes[0] / 128;     // 100000
    const int E = in_sizes[1] / 2;       // 1600000

    float *bufY, *bufAgg;
    int *cnt, *buck;
    cudaGetSymbolAddress((void**)&bufY, g_bufY);
    cudaGetSymbolAddress((void**)&bufAgg, g_bufAgg);
    cudaGetSymbolAddress((void**)&cnt, g_cnt);
    cudaGetSymbolAddress((void**)&buck, g_buck);

    const int smem1 = (64 * (128 + 4) + 128 * 64) * (int)sizeof(float); // 66560
    const int smem2 = (64 * (64 + 4)  + 64 * 64)  * (int)sizeof(float); // 33792
    cudaFuncSetAttribute((const void*)gemm64_kernel<128, false>,
                         cudaFuncAttributeMaxDynamicSharedMemorySize, smem1);
    cudaFuncSetAttribute((const void*)gemm64_kernel<64, true>,
                         cudaFuncAttributeMaxDynamicSharedMemorySize, smem2);

    const int gb  = (N + 63) / 64;
    const int agb = (int)(((long long)N * 16 + 255) / 256);

    // Build neighbor lists (cnt zeroed by previous call's gather_head,
    // or by static zero-init on the very first call)
    build_kernel<<<(E / 2 + 255) / 256, 256>>>(ei, cnt, buck, E);

    // conv1: y1 = x@W1 ; agg1 = y1 + gather(y1)
    gemm64_kernel<128, false><<<gb, 256, smem1>>>(x, W1, nullptr, bufY, N);
    gather_kernel<<<agb, 256>>>(cnt, buck, bufY, bufAgg, N);
    // conv2: y2 = relu(agg1+b1)@W2
    gemm64_kernel<64, true><<<gb, 256, smem2>>>(bufAgg, W2, b1, bufY, N);
    // fused: agg2 = y2 + gather(y2); head MLP -> out; cnt reset
    gather_head_kernel<<<agb, 256>>>(cnt, buck, bufY, b2, W3, b3, W4, b4, out, N);
}

// round 13
// speedup vs baseline: 1.2421x; 1.1071x over previous
#include <cuda_runtime.h>
#include <cuda_fp16.h>

#define MAXN 100000
#define HID 64
#define CAP 64   // neighbor-list capacity per node (deg ~ Poisson(16))

// Scratch (no cudaMalloc allowed). __device__ globals zero-init; g_cnt is
// re-zeroed by gather_head_kernel each call, keeping the invariant across
// graph replays.
__device__ __half g_bufY[(size_t)MAXN * HID];   // 12.8 MB (fp16 activations)
__device__ float  g_bufAgg[(size_t)MAXN * HID]; // 25.6 MB (fp32 aggregates)
__device__ int    g_cnt[MAXN];                  // 0.4 MB
__device__ int    g_buck[(size_t)MAXN * CAP];   // 25.6 MB

typedef unsigned long long ull;

// ---------------------------------------------------------------------------
// f32x2 packed helpers (Blackwell FFMA2 — PTX-only, 2 FMAs per issue)
// ---------------------------------------------------------------------------
__device__ __forceinline__ void fma2(ull& d, ull a, ull b) {
    asm("fma.rn.f32x2 %0, %1, %2, %0;" : "+l"(d) : "l"(a), "l"(b));
}
__device__ __forceinline__ ull dup2(float a) {
    ull r;
    asm("mov.b64 %0, {%1, %1};" : "=l"(r) : "f"(a));
    return r;
}
__device__ __forceinline__ ull pack2(float lo, float hi) {
    ull r;
    asm("mov.b64 %0, {%1, %2};" : "=l"(r) : "f"(lo), "f"(hi));
    return r;
}
__device__ __forceinline__ float2 unpack2(ull v) {
    float2 f;
    asm("mov.b64 {%0, %1}, %2;" : "=f"(f.x), "=f"(f.y) : "l"(v));
    return f;
}

// ---------------------------------------------------------------------------
// Build body: cnt[d]=in-degree, buck[d*CAP+slot]=src. Called from gemm1
// blocks as a post-tile phase (overlaps with other blocks' FMA work).
// ---------------------------------------------------------------------------
__device__ __forceinline__ void build_slice(const int* __restrict__ ei,
                                            int* cnt, int* buck,
                                            int E, int blk) {
    int e0 = blk * 1024 + threadIdx.x * 4;
    if (e0 + 3 < E) {
        int4 s4 = __ldg((const int4*)(ei + e0));
        int4 d4 = __ldg((const int4*)(ei + E + e0));
        int t0 = atomicAdd(&cnt[d4.x], 1);
        if (t0 < CAP) buck[(size_t)d4.x * CAP + t0] = s4.x;
        int t1 = atomicAdd(&cnt[d4.y], 1);
        if (t1 < CAP) buck[(size_t)d4.y * CAP + t1] = s4.y;
        int t2 = atomicAdd(&cnt[d4.z], 1);
        if (t2 < CAP) buck[(size_t)d4.z * CAP + t2] = s4.z;
        int t3 = atomicAdd(&cnt[d4.w], 1);
        if (t3 < CAP) buck[(size_t)d4.w * CAP + t3] = s4.w;
    } else {
        for (int e = e0; e < E && e < e0 + 4; ++e) {
            int s = __ldg(&ei[e]);
            int d = __ldg(&ei[E + e]);
            int sl = atomicAdd(&cnt[d], 1);
            if (sl < CAP) buck[(size_t)d * CAP + sl] = s;
        }
    }
}

// ---------------------------------------------------------------------------
// GEMM body (R6-proven compute core): out[64 rows, 64] = act(X) @ W
// fp16 epilogue. BUILD=true appends the edge-bucket slice (gemm1 only).
// ---------------------------------------------------------------------------
template<int K, bool PRE, bool BUILD>
__global__ void gemm64_kernel(const float* X,
                              const float* __restrict__ W,
                              const float* __restrict__ bpre,
                              __half* __restrict__ outY,
                              int N,
                              const int* __restrict__ ei,
                              int* cnt, int* buck, int E) {
    constexpr int LD = K + 4;
    constexpr int KV = K / 4;
    extern __shared__ float smem[];
    float* Xs = smem;                    // [64][LD]
    float* Ws = smem + 64 * LD;          // [K][64]

    const int tid  = threadIdx.x;
    const int row0 = blockIdx.x * 64;

    {   // W tile
        float4* Ws4 = (float4*)Ws;
        const float4* Wg4 = (const float4*)W;
        for (int i = tid; i < K * 16; i += 256) Ws4[i] = Wg4[i];
    }
    // X tile, optional fused relu(x+b)
    for (int i = tid; i < 64 * KV; i += 256) {
        int r  = i / KV;
        int c4 = i % KV;
        float4 v = make_float4(0.f, 0.f, 0.f, 0.f);
        if (row0 + r < N)
            v = *(const float4*)(X + (size_t)(row0 + r) * K + c4 * 4);
        if (PRE) {
            v.x = fmaxf(v.x + __ldg(&bpre[c4 * 4 + 0]), 0.f);
            v.y = fmaxf(v.y + __ldg(&bpre[c4 * 4 + 1]), 0.f);
            v.z = fmaxf(v.z + __ldg(&bpre[c4 * 4 + 2]), 0.f);
            v.w = fmaxf(v.w + __ldg(&bpre[c4 * 4 + 3]), 0.f);
        }
        *(float4*)(Xs + r * LD + c4 * 4) = v;
    }
    __syncthreads();

    const int tx = tid & 15;             // cols tx*4 .. tx*4+3  (2 col-pairs)
    const int ty = tid >> 4;             // rows ty*4 .. ty*4+3

    ull acc[4][2];
    #pragma unroll
    for (int i = 0; i < 4; ++i) { acc[i][0] = 0ull; acc[i][1] = 0ull; }

    const ull* Wsq = (const ull*)Ws;
    #pragma unroll 8
    for (int k = 0; k < K; ++k) {
        ull w01 = Wsq[k * 32 + tx * 2 + 0];
        ull w23 = Wsq[k * 32 + tx * 2 + 1];
        #pragma unroll
        for (int i = 0; i < 4; ++i) {
            ull aa = dup2(Xs[(ty * 4 + i) * LD + k]);
            fma2(acc[i][0], aa, w01);
            fma2(acc[i][1], aa, w23);
        }
    }

    #pragma unroll
    for (int i = 0; i < 4; ++i) {
        int r = row0 + ty * 4 + i;
        if (r < N) {
            float2 p0 = unpack2(acc[i][0]);
            float2 p1 = unpack2(acc[i][1]);
            __half2 h0 = __floats2half2_rn(p0.x, p0.y);
            __half2 h1 = __floats2half2_rn(p1.x, p1.y);
            uint2 st;
            st.x = *(unsigned*)&h0;
            st.y = *(unsigned*)&h1;
            *(uint2*)(outY + (size_t)r * 64 + tx * 4) = st;
        }
    }

    if (BUILD) build_slice(ei, cnt, buck, E, blockIdx.x);
}

// ---------------------------------------------------------------------------
// Gather core (fp16 Y): 8 threads/node, each owns 8 halves (16B) per row.
// acc in fp32. 4-way unrolled neighbor loop, 2 accumulator sets.
// ---------------------------------------------------------------------------
__device__ __forceinline__ void acc_row(float2 a[4], uint4 u) {
    a[0] = make_float2(a[0].x, a[0].y);  // no-op, keeps compiler happy
    float2 f0 = __half22float2(*(__half2*)&u.x);
    float2 f1 = __half22float2(*(__half2*)&u.y);
    float2 f2 = __half22float2(*(__half2*)&u.z);
    float2 f3 = __half22float2(*(__half2*)&u.w);
    a[0].x += f0.x; a[0].y += f0.y;
    a[1].x += f1.x; a[1].y += f1.y;
    a[2].x += f2.x; a[2].y += f2.y;
    a[3].x += f3.x; a[3].y += f3.y;
}

__device__ __forceinline__ void gather_row8(const int* __restrict__ cnt,
                                            const int* __restrict__ buck,
                                            const __half* __restrict__ Y,
                                            int n, int c, float2 acc[4]) {
    uint4 u = __ldg((const uint4*)(Y + (size_t)n * 64) + c);   // self term
    float2 f0 = __half22float2(*(__half2*)&u.x);
    float2 f1 = __half22float2(*(__half2*)&u.y);
    float2 f2 = __half22float2(*(__half2*)&u.z);
    float2 f3 = __half22float2(*(__half2*)&u.w);
    acc[0] = f0; acc[1] = f1; acc[2] = f2; acc[3] = f3;
    float2 acc2[4] = {{0.f,0.f},{0.f,0.f},{0.f,0.f},{0.f,0.f}};

    int m = min(__ldg(&cnt[n]), CAP);
    const int* b = buck + (size_t)n * CAP;

    int j = 0;
    for (; j + 4 <= m; j += 4) {
        int s0 = __ldg(&b[j]);
        int s1 = __ldg(&b[j + 1]);
        int s2 = __ldg(&b[j + 2]);
        int s3 = __ldg(&b[j + 3]);
        uint4 u0 = __ldg((const uint4*)(Y + (size_t)s0 * 64) + c);
        uint4 u1 = __ldg((const uint4*)(Y + (size_t)s1 * 64) + c);
        uint4 u2 = __ldg((const uint4*)(Y + (size_t)s2 * 64) + c);
        uint4 u3 = __ldg((const uint4*)(Y + (size_t)s3 * 64) + c);
        acc_row(acc, u0);
        acc_row(acc2, u1);
        acc_row(acc, u2);
        acc_row(acc2, u3);
    }
    for (; j < m; ++j) {
        int s0 = __ldg(&b[j]);
        uint4 u0 = __ldg((const uint4*)(Y + (size_t)s0 * 64) + c);
        acc_row(acc, u0);
    }
    #pragma unroll
    for (int i = 0; i < 4; ++i) {
        acc[i].x += acc2[i].x;
        acc[i].y += acc2[i].y;
    }
}

// Layer-1 aggregation: Agg (fp32) = Y + gather(Y)
__global__ void gather_kernel(const int* __restrict__ cnt,
                              const int* __restrict__ buck,
                              const __half* __restrict__ Y,
                              float* __restrict__ Agg,
                              int N) {
    int t = blockIdx.x * blockDim.x + threadIdx.x;
    int n = t >> 3;
    int c = t & 7;
    if (n >= N) return;
    float2 acc[4];
    gather_row8(cnt, buck, Y, n, c, acc);
    float* dst = Agg + (size_t)n * 64 + c * 8;
    *(float4*)(dst + 0) = make_float4(acc[0].x, acc[0].y, acc[1].x, acc[1].y);
    *(float4*)(dst + 4) = make_float4(acc[2].x, acc[2].y, acc[3].x, acc[3].y);
}

// ---------------------------------------------------------------------------
// Fused layer-2 aggregation + MLP head (+ cnt reset for next call)
// 8 threads/node; each thread owns 8 h2 values and 2 of the 16 W3 outputs.
// ---------------------------------------------------------------------------
__global__ void gather_head_kernel(int* __restrict__ cnt,
                                   const int* __restrict__ buck,
                                   const __half* __restrict__ Y,
                                   const float* __restrict__ b2,
                                   const float* __restrict__ W3,
                                   const float* __restrict__ b3,
                                   const float* __restrict__ W4,
                                   const float* __restrict__ b4,
                                   float* __restrict__ out,
                                   int N) {
    __shared__ ull   W3p[32 * 16];       // [kp][c] = (W3[2kp][c], W3[2kp+1][c])
    __shared__ float b2s[64], b3s[16], W4s[16];
    __shared__ float h2s[32][64];        // 32 nodes per 256-thread block

    const int tid = threadIdx.x;
    for (int i = tid; i < 32 * 16; i += 256) {
        int kp = i >> 4, c = i & 15;
        W3p[i] = pack2(__ldg(&W3[(2 * kp) * 16 + c]),
                       __ldg(&W3[(2 * kp + 1) * 16 + c]));
    }
    if (tid < 64) b2s[tid] = b2[tid];
    if (tid < 16) { b3s[tid] = b3[tid]; W4s[tid] = W4[tid]; }
    __syncthreads();

    int t = blockIdx.x * 256 + tid;
    int n = t >> 3;
    int c = t & 7;                       // owns halves 8c..8c+7 / outs {c,c+8}
    int g = tid >> 3;                    // node slot within block
    if (n >= N) return;

    float2 acc[4];
    gather_row8(cnt, buck, Y, n, c, acc);

    // h2 = relu(acc + b2)
    float h[8];
    #pragma unroll
    for (int i = 0; i < 4; ++i) {
        h[2 * i + 0] = fmaxf(acc[i].x + b2s[8 * c + 2 * i + 0], 0.f);
        h[2 * i + 1] = fmaxf(acc[i].y + b2s[8 * c + 2 * i + 1], 0.f);
    }
    *(float4*)(&h2s[g][8 * c + 0]) = make_float4(h[0], h[1], h[2], h[3]);
    *(float4*)(&h2s[g][8 * c + 4]) = make_float4(h[4], h[5], h[6], h[7]);
    __syncwarp();

    // thread c computes W3 outputs c and c+8 (k-pairs via FFMA2)
    ull a2_0 = 0ull, a2_1 = 0ull;
    const ull* hq = (const ull*)h2s[g];
    #pragma unroll 8
    for (int kp = 0; kp < 32; ++kp) {
        ull hv = hq[kp];
        fma2(a2_0, hv, W3p[kp * 16 + c]);
        fma2(a2_1, hv, W3p[kp * 16 + c + 8]);
    }
    float2 p0 = unpack2(a2_0);
    float2 p1 = unpack2(a2_1);
    float a3_0 = b3s[c]     + p0.x + p0.y;
    float a3_1 = b3s[c + 8] + p1.x + p1.y;
    float v = fmaxf(a3_0, 0.f) * W4s[c] + fmaxf(a3_1, 0.f) * W4s[c + 8];

    #pragma unroll
    for (int off = 4; off > 0; off >>= 1)
        v += __shfl_xor_sync(0xffffffffu, v, off, 8);

    if (c == 0) {
        out[n] = v + __ldg(&b4[0]);
        cnt[n] = 0;                      // reset for next call / graph replay
    }
}

// ---------------------------------------------------------------------------
extern "C" void kernel_launch(void* const* d_in, const int* in_sizes, int n_in,
                              void* d_out, int out_size) {
    const float* x  = (const float*)d_in[0];
    const int*   ei = (const int*)d_in[1];     // int32 (JAX x64 disabled)
    const float* W1 = (const float*)d_in[2];
    const float* b1 = (const float*)d_in[3];
    const float* W2 = (const float*)d_in[4];
    const float* b2 = (const float*)d_in[5];
    const float* W3 = (const float*)d_in[6];
    const float* b3 = (const float*)d_in[7];
    const float* W4 = (const float*)d_in[8];
    const float* b4 = (const float*)d_in[9];
    float* out = (float*)d_out;

    const int N = in_sizes[0] / 128;     // 100000
    const int E = in_sizes[1] / 2;       // 1600000

    __half* bufY;
    float*  bufAgg;
    int *cnt, *buck;
    cudaGetSymbolAddress((void**)&bufY, g_bufY);
    cudaGetSymbolAddress((void**)&bufAgg, g_bufAgg);
    cudaGetSymbolAddress((void**)&cnt, g_cnt);
    cudaGetSymbolAddress((void**)&buck, g_buck);

    const int smem1 = (64 * (128 + 4) + 128 * 64) * (int)sizeof(float); // 66560
    const int smem2 = (64 * (64 + 4)  + 64 * 64)  * (int)sizeof(float); // 33792
    cudaFuncSetAttribute((const void*)gemm64_kernel<128, false, true>,
                         cudaFuncAttributeMaxDynamicSharedMemorySize, smem1);
    cudaFuncSetAttribute((const void*)gemm64_kernel<64, true, false>,
                         cudaFuncAttributeMaxDynamicSharedMemorySize, smem2);

    const int gb  = (N + 63) / 64;                          // 1563 (>= E/1024)
    const int agb = (int)(((long long)N * 8 + 255) / 256);

    // conv1: y1 = x@W1 (fp16 out) + per-block edge-bucket build appended
    gemm64_kernel<128, false, true><<<gb, 256, smem1>>>(
        x, W1, nullptr, bufY, N, ei, cnt, buck, E);
    // agg1 (fp32) = y1 + gather(y1)
    gather_kernel<<<agb, 256>>>(cnt, buck, bufY, bufAgg, N);
    // conv2: y2 = relu(agg1+b1)@W2 (fp16 out)
    gemm64_kernel<64, true, false><<<gb, 256, smem2>>>(
        bufAgg, W2, b1, bufY, N, nullptr, nullptr, nullptr, 0);
    // fused: agg2 = y2 + gather(y2); head MLP -> out; cnt reset
    gather_head_kernel<<<agb, 256>>>(cnt, buck, bufY, b2, W3, b3, W4, b4, out, N);
}